// round 16
// baseline (speedup 1.0000x reference)
#include <cuda_runtime.h>
#include <cstdint>
#include <cstddef>

// ---------------------------------------------------------------------------
// MultiheadAttention (equivariant graph attention), fp32, round 16.
// N=50000 nodes, E=800000 edges, D_IN=128, SH=16, EA=16, H=8, DQ=DK=64, DV=128
//
// R16 vs R15 (1751us; edgek 638 @3CTAs + edgev ~985 @2CTAs, equal per-FLOP
// efficiency -> edgev NOT occupancy-bound):
//  * edgek+edgev RE-FUSED into one kernel with the proven internals:
//    - stage EA/SH/idx ONCE (was twice)
//    - ealpha stays in smem (kills 51MB global round-trip)
//    - x_src gathered twice but second gather is an L1 HIT (same CTA)
//    - one launch fewer; K-part 2 CTAs (R15 datum: occupancy-neutral)
//    smem 62.5KB, launch_bounds(256,2); V-tail register shape identical to
//    R11's proven no-spill form.
//  * zero+convert+setup fused into one prep kernel.
// ---------------------------------------------------------------------------

#define NMAX 50000
#define EMAX 800000

__device__ float g_q2[NMAX * 64];
__device__ float g_Wq2[128 * 64];
__device__ float g_WangkT[16 * 128];
__device__ float g_WangvT[16 * 128];
__device__ float g_denom[NMAX * 8];
__device__ float g_numer[NMAX * 128];
__device__ int   g_eidx[2 * EMAX];

__device__ __forceinline__ void red_add_v4(float* p, float4 v) {
    asm volatile("red.global.add.v4.f32 [%0], {%1,%2,%3,%4};"
                 :: "l"(p), "f"(v.x), "f"(v.y), "f"(v.z), "f"(v.w)
                 : "memory");
}

// Edge-kernel map: 256 threads -> 16 ty x 16 tx; warp = 8 ty x 4 tx.
// lane bit0 == tx bit0 (alpha shfl pairing). Rows owned: r = 16*i + ty.
__device__ __forceinline__ void thread_mapE(int t, int& ty, int& tx) {
    const int lane = t & 31, w = t >> 5;
    tx = ((w & 3) << 2) | (lane & 3);
    ty = ((w >> 2) << 3) | (lane >> 2);
}

// ---------------------------------------------------------------------------
// Fused prep: zero accumulators + idx dtype detect/convert + weight setup.
// ---------------------------------------------------------------------------
__global__ void prep_kernel(const void* __restrict__ eidx, int twoE, int n,
                            const float* __restrict__ Wq,
                            const float* __restrict__ Wdot,
                            const float* __restrict__ Wang_k,
                            const float* __restrict__ Wang_v) {
    const int t = threadIdx.x;
    const int gi = blockIdx.x * blockDim.x + t;
    const int gstride = gridDim.x * blockDim.x;

    // zero denom/numer
    const float4 z = make_float4(0.f, 0.f, 0.f, 0.f);
    for (int j = gi; j < n * 2; j += gstride) reinterpret_cast<float4*>(g_denom)[j] = z;
    for (int j = gi; j < n * 32; j += gstride) reinterpret_cast<float4*>(g_numer)[j] = z;

    // idx detect (per-block, first 512 words) + convert
    {
        const int* pi = (const int*)eidx;
        int w = 2 * t + 1;
        int nz = (w < twoE && w < 512) ? (pi[w] != 0) : 0;
        __shared__ int any;
        if (t == 0) any = 0;
        __syncthreads();
        if (nz) any = 1;
        __syncthreads();
        const bool is64 = (any == 0);
        if (gi < twoE) {
            long long v = is64 ? __ldg((const long long*)eidx + gi)
                               : (long long)__ldg((const int*)eidx + gi);
            g_eidx[gi] = (int)v;
        }
    }

    // setup (block 0 only)
    if (blockIdx.x == 0) {
        for (int o = t; o < 128 * 64; o += 256) {
            int d = o >> 6, hj = o & 63, h = hj >> 3, j = hj & 7;
            float s = 0.f;
#pragma unroll
            for (int i = 0; i < 8; ++i)
                s = fmaf(Wq[d * 64 + h * 8 + i], Wdot[i * 8 + j], s);
            g_Wq2[o] = s;
        }
        for (int o = t; o < 16 * 128; o += 256) {
            int s_ = o >> 7, d = o & 127;
            g_WangkT[o] = Wang_k[d * 16 + s_];
            g_WangvT[o] = Wang_v[d * 16 + s_];
        }
    }
}

// ---------------------------------------------------------------------------
// Edge GEMM core (interleaved rows r=16i+ty): C[64,16*CPT] = A[64,KD]@B
// A in smem, LDA must be 4*odd mod 32 (20/68/132). B via __ldg, 64B/warp.
// ---------------------------------------------------------------------------
template <int KD, int LDA, int CPT>
__device__ __forceinline__ void gemmE(const float* __restrict__ As,
                                      const float* __restrict__ Bg,
                                      float (&acc)[4][CPT], int ty, int tx) {
    constexpr int NO = 16 * CPT;
#pragma unroll
    for (int i = 0; i < 4; i++)
#pragma unroll
        for (int j = 0; j < CPT; j++) acc[i][j] = 0.f;

#pragma unroll
    for (int d = 0; d < KD; d += 4) {
        float a[4][4];
#pragma unroll
        for (int i = 0; i < 4; i++)
            *(float4*)&a[i][0] = *(const float4*)(As + (16 * i + ty) * LDA + d);
#pragma unroll
        for (int dd = 0; dd < 4; ++dd) {
            const float4* B4 = reinterpret_cast<const float4*>(Bg + (size_t)(d + dd) * NO);
            float4 b0 = __ldg(B4 + tx);
#pragma unroll
            for (int i = 0; i < 4; i++) {
                acc[i][0] = fmaf(a[i][dd], b0.x, acc[i][0]);
                acc[i][1] = fmaf(a[i][dd], b0.y, acc[i][1]);
                acc[i][2] = fmaf(a[i][dd], b0.z, acc[i][2]);
                acc[i][3] = fmaf(a[i][dd], b0.w, acc[i][3]);
            }
            if (CPT == 8) {
                float4 b1 = __ldg(B4 + 16 + tx);
#pragma unroll
                for (int i = 0; i < 4; i++) {
                    acc[i][4] = fmaf(a[i][dd], b1.x, acc[i][4]);
                    acc[i][5] = fmaf(a[i][dd], b1.y, acc[i][5]);
                    acc[i][6] = fmaf(a[i][dd], b1.z, acc[i][6]);
                    acc[i][7] = fmaf(a[i][dd], b1.w, acc[i][7]);
                }
            }
        }
    }
}

// R6-style core for q2/out kernels (rows 4ty+i, ty = t>>4).
template <int KD, int LDA, int CPT>
__device__ __forceinline__ void gemm_core(const float* __restrict__ As,
                                          const float* __restrict__ Bg,
                                          float (&acc)[4][CPT], int ty, int tx) {
    constexpr int NO = 16 * CPT;
#pragma unroll
    for (int i = 0; i < 4; i++)
#pragma unroll
        for (int j = 0; j < CPT; j++) acc[i][j] = 0.f;

#pragma unroll
    for (int d = 0; d < KD; d += 4) {
        float a[4][4];
#pragma unroll
        for (int i = 0; i < 4; i++)
            *(float4*)&a[i][0] = *(const float4*)(As + (4 * ty + i) * LDA + d);
#pragma unroll
        for (int dd = 0; dd < 4; ++dd) {
            const float4* B4 = reinterpret_cast<const float4*>(Bg + (size_t)(d + dd) * NO);
            float4 b0 = __ldg(B4 + tx);
#pragma unroll
            for (int i = 0; i < 4; i++) {
                acc[i][0] = fmaf(a[i][dd], b0.x, acc[i][0]);
                acc[i][1] = fmaf(a[i][dd], b0.y, acc[i][1]);
                acc[i][2] = fmaf(a[i][dd], b0.z, acc[i][2]);
                acc[i][3] = fmaf(a[i][dd], b0.w, acc[i][3]);
            }
            if (CPT == 8) {
                float4 b1 = __ldg(B4 + 16 + tx);
#pragma unroll
                for (int i = 0; i < 4; i++) {
                    acc[i][4] = fmaf(a[i][dd], b1.x, acc[i][4]);
                    acc[i][5] = fmaf(a[i][dd], b1.y, acc[i][5]);
                    acc[i][6] = fmaf(a[i][dd], b1.z, acc[i][6]);
                    acc[i][7] = fmaf(a[i][dd], b1.w, acc[i][7]);
                }
            }
        }
    }
}

// ---------------------------------------------------------------------------
// q2 = node_attr @ Wq2   [n,128]@[128,64]
// ---------------------------------------------------------------------------
__global__ void __launch_bounds__(256) q2_kernel(const float* __restrict__ na, int n) {
    __shared__ float As[64 * 132];
    const int t = threadIdx.x, ty = t >> 4, tx = t & 15;
    const int n0 = blockIdx.x * 64;
    {
        const int r = t >> 2, seg = t & 3;
        const int nn = n0 + r;
#pragma unroll
        for (int q = 0; q < 8; q++) {
            const int d = seg * 32 + q * 4;
            float4 v = make_float4(0.f, 0.f, 0.f, 0.f);
            if (nn < n) v = __ldg((const float4*)(na + (size_t)nn * 128 + d));
            *(float4*)(As + r * 132 + d) = v;
        }
    }
    __syncthreads();
    float acc[4][4];
    gemm_core<128, 132, 4>(As, g_Wq2, acc, ty, tx);
#pragma unroll
    for (int i = 0; i < 4; i++) {
        const int nn = n0 + 4 * ty + i;
        if (nn < n)
            *(float4*)(g_q2 + (size_t)nn * 64 + tx * 4) =
                make_float4(acc[i][0], acc[i][1], acc[i][2], acc[i][3]);
    }
}

// ---------------------------------------------------------------------------
// Fused edge kernel: 64 edges/block, 256 threads. smem = 16000 floats = 62.5KB.
// launch_bounds(256,2) (V-tail regs ~110, same as proven R11 edgev).
// layout: EA[64x20] SH[64x20] G[64x132] H[64x68] EAL[512] idx[128]
// phases: stage | Hk | {XGk,Rk} | bigK+alpha->EAL | {denom scatter, Hv} |
//         {XGv,Rv} | bigV+numer scatter
// ---------------------------------------------------------------------------
#define F_EA  0
#define F_SH  (64 * 20)
#define F_G   (2 * 64 * 20)
#define F_H   (F_G + 64 * 132)
#define F_EAL (F_H + 64 * 68)
#define F_IDX (F_EAL + 64 * 8)
#define F_SMEM (F_IDX + 128)

__global__ void __launch_bounds__(256, 2) edge_kernel(
    const float* __restrict__ na, const float* __restrict__ ea,
    const float* __restrict__ shp,
    const float* __restrict__ Wlin_k, const float* __restrict__ W1k,
    const float* __restrict__ b1k, const float* __restrict__ W2k,
    const float* __restrict__ Wlin_v, const float* __restrict__ W1v,
    const float* __restrict__ b1v, const float* __restrict__ W2v,
    int E) {
    extern __shared__ float sm[];
    int* idx = (int*)(sm + F_IDX);
    const int t = threadIdx.x;
    int ty, tx; thread_mapE(t, ty, tx);
    const int e0 = blockIdx.x * 64;

    // S0: stage EA/SH/idx once
    {
        if (t < 64) {
            const int ge = e0 + t;
            int s = 0, d_ = 0;
            if (ge < E) { s = g_eidx[ge]; d_ = g_eidx[E + ge]; }
            idx[t] = s;
            idx[64 + t] = d_;
        }
        const int e = t >> 2, part = t & 3;
        const int ge = e0 + e;
        float4 va = make_float4(0.f, 0.f, 0.f, 0.f), vs = va;
        if (ge < E) {
            va = __ldg((const float4*)(ea + (size_t)ge * 16) + part);
            vs = __ldg((const float4*)(shp + (size_t)ge * 16) + part);
        }
        *(float4*)(sm + F_EA + e * 20 + part * 4) = va;
        *(float4*)(sm + F_SH + e * 20 + part * 4) = vs;
    }
    __syncthreads();

    // S1: Hk = relu(EA@W1k + b1k) -> H
    {
        float acc[4][4];
        gemmE<16, 20, 4>(sm + F_EA, W1k, acc, ty, tx);
        float4 bk = __ldg((const float4*)(b1k) + tx);
#pragma unroll
        for (int i = 0; i < 4; i++)
            *(float4*)(sm + F_H + (16 * i + ty) * 68 + tx * 4) =
                make_float4(fmaxf(acc[i][0] + bk.x, 0.f), fmaxf(acc[i][1] + bk.y, 0.f),
                            fmaxf(acc[i][2] + bk.z, 0.f), fmaxf(acc[i][3] + bk.w, 0.f));
    }
    __syncthreads();

    // S2: XGk = x_src * (SH @ Wang_k^T) -> G;  Rk = H @ W2k -> regs
    {
        float acc[4][8];
        gemmE<16, 20, 8>(sm + F_SH, g_WangkT, acc, ty, tx);
#pragma unroll
        for (int i = 0; i < 4; i++) {
            const int r = 16 * i + ty;
            const float* xb = na + (size_t)idx[r] * 128;
            float4 x0 = __ldg((const float4*)(xb + tx * 4));
            float4 x1 = __ldg((const float4*)(xb + 64 + tx * 4));
            *(float4*)(sm + F_G + r * 132 + tx * 4) =
                make_float4(acc[i][0] * x0.x, acc[i][1] * x0.y,
                            acc[i][2] * x0.z, acc[i][3] * x0.w);
            *(float4*)(sm + F_G + r * 132 + 64 + tx * 4) =
                make_float4(acc[i][4] * x1.x, acc[i][5] * x1.y,
                            acc[i][6] * x1.z, acc[i][7] * x1.w);
        }
    }
    float rk[4][4];
    gemmE<64, 68, 4>(sm + F_H, W2k, rk, ty, tx);
    __syncthreads();

    // S3: K = (XGk @ Wlin_k) * Rk; alpha; ealpha -> EAL (smem, stays local)
    {
        float acc[4][4];
        gemmE<128, 132, 4>(sm + F_G, Wlin_k, acc, ty, tx);
#pragma unroll
        for (int i = 0; i < 4; i++) {
            const int r = 16 * i + ty;
            float4 q2v = __ldg((const float4*)(g_q2 + (size_t)idx[64 + r] * 64 + tx * 4));
            float p = acc[i][0] * rk[i][0] * q2v.x + acc[i][1] * rk[i][1] * q2v.y +
                      acc[i][2] * rk[i][2] * q2v.z + acc[i][3] * rk[i][3] * q2v.w;
            p += __shfl_xor_sync(0xffffffffu, p, 1);   // lane bit0 == tx bit0
            if ((tx & 1) == 0) sm[F_EAL + r * 8 + (tx >> 1)] = __expf(p);
        }
    }
    __syncthreads();

    // S4: denominator scatter (t<128) overlapped with Hv GEMM
    if (t < 128) {
        const int e = t >> 1, half = t & 1;
        if (e0 + e < E) {
            float4 v = *(float4*)(sm + F_EAL + e * 8 + half * 4);
            red_add_v4(g_denom + (size_t)idx[64 + e] * 8 + half * 4, v);
        }
    }
    {
        float acc[4][4];
        gemmE<16, 20, 4>(sm + F_EA, W1v, acc, ty, tx);
        float4 bv = __ldg((const float4*)(b1v) + tx);
#pragma unroll
        for (int i = 0; i < 4; i++)
            *(float4*)(sm + F_H + (16 * i + ty) * 68 + tx * 4) =
                make_float4(fmaxf(acc[i][0] + bv.x, 0.f), fmaxf(acc[i][1] + bv.y, 0.f),
                            fmaxf(acc[i][2] + bv.z, 0.f), fmaxf(acc[i][3] + bv.w, 0.f));
    }
    __syncthreads();

    // S5: XGv = x_src * (SH @ Wang_v^T) -> G (x gather now L1-hot);
    //     Rv = H @ W2v -> regs
    {
        float acc[4][8];
        gemmE<16, 20, 8>(sm + F_SH, g_WangvT, acc, ty, tx);
#pragma unroll
        for (int i = 0; i < 4; i++) {
            const int r = 16 * i + ty;
            const float* xb = na + (size_t)idx[r] * 128;
            float4 x0 = __ldg((const float4*)(xb + tx * 4));
            float4 x1 = __ldg((const float4*)(xb + 64 + tx * 4));
            *(float4*)(sm + F_G + r * 132 + tx * 4) =
                make_float4(acc[i][0] * x0.x, acc[i][1] * x0.y,
                            acc[i][2] * x0.z, acc[i][3] * x0.w);
            *(float4*)(sm + F_G + r * 132 + 64 + tx * 4) =
                make_float4(acc[i][4] * x1.x, acc[i][5] * x1.y,
                            acc[i][6] * x1.z, acc[i][7] * x1.w);
        }
    }
    float rv[4][8];
    gemmE<64, 68, 8>(sm + F_H, W2v, rv, ty, tx);
    __syncthreads();

    // S6: V = (XGv @ Wlin_v) * Rv; numer[dst] += ealpha[h] * V
    {
        float acc[4][8];
        gemmE<128, 132, 8>(sm + F_G, Wlin_v, acc, ty, tx);
        const int h0 = tx >> 2, h1 = 4 + (tx >> 2);   // warp-uniform heads
#pragma unroll
        for (int i = 0; i < 4; i++) {
            const int r = 16 * i + ty;
            if (e0 + r < E) {
                const float eh0 = sm[F_EAL + r * 8 + h0];
                const float eh1 = sm[F_EAL + r * 8 + h1];
                float* np = g_numer + (size_t)idx[64 + r] * 128;
                red_add_v4(np + tx * 4,
                           make_float4(acc[i][0] * rv[i][0] * eh0, acc[i][1] * rv[i][1] * eh0,
                                       acc[i][2] * rv[i][2] * eh0, acc[i][3] * rv[i][3] * eh0));
                red_add_v4(np + 64 + tx * 4,
                           make_float4(acc[i][4] * rv[i][4] * eh1, acc[i][5] * rv[i][5] * eh1,
                                       acc[i][6] * rv[i][6] * eh1, acc[i][7] * rv[i][7] * eh1));
            }
        }
    }
}

// ---------------------------------------------------------------------------
// out = (numer / denom per head) @ Wout
// ---------------------------------------------------------------------------
__global__ void __launch_bounds__(256) out_kernel(const float* __restrict__ Wout,
                                                  float* __restrict__ out, int n) {
    __shared__ float As[64 * 132];
    const int t = threadIdx.x, ty = t >> 4, tx = t & 15;
    const int n0 = blockIdx.x * 64;
    {
        const int r = t >> 2, seg = t & 3;
        const int nn = n0 + r;
#pragma unroll
        for (int q = 0; q < 8; q++) {
            const int d = seg * 32 + 4 * q;
            float4 v = make_float4(0.f, 0.f, 0.f, 0.f);
            if (nn < n) {
                v = *(const float4*)(g_numer + (size_t)nn * 128 + d);
                float den = g_denom[(size_t)nn * 8 + (d >> 4)];
                float inv = (den > 0.f) ? __frcp_rn(den) : 0.f;
                v.x *= inv; v.y *= inv; v.z *= inv; v.w *= inv;
            }
            *(float4*)(As + r * 132 + d) = v;
        }
    }
    __syncthreads();
    float acc[4][8];
    gemm_core<128, 132, 8>(As, Wout, acc, ty, tx);
#pragma unroll
    for (int i = 0; i < 4; i++) {
        const int m = n0 + 4 * ty + i;
        if (m < n) {
            *(float4*)(out + (size_t)m * 128 + tx * 4) =
                make_float4(acc[i][0], acc[i][1], acc[i][2], acc[i][3]);
            *(float4*)(out + (size_t)m * 128 + 64 + tx * 4) =
                make_float4(acc[i][4], acc[i][5], acc[i][6], acc[i][7]);
        }
    }
}

// ---------------------------------------------------------------------------
extern "C" void kernel_launch(void* const* d_in, const int* in_sizes, int n_in,
                              void* d_out, int out_size) {
    const float* na      = (const float*)d_in[0];
    const float* ea      = (const float*)d_in[1];
    const float* shp     = (const float*)d_in[2];
    const float* Wq      = (const float*)d_in[3];
    const float* Wang_k  = (const float*)d_in[4];
    const float* Wlin_k  = (const float*)d_in[5];
    const float* W1k     = (const float*)d_in[6];
    const float* b1k     = (const float*)d_in[7];
    const float* W2k     = (const float*)d_in[8];
    const float* Wang_v  = (const float*)d_in[9];
    const float* Wlin_v  = (const float*)d_in[10];
    const float* W1v     = (const float*)d_in[11];
    const float* b1v     = (const float*)d_in[12];
    const float* W2v     = (const float*)d_in[13];
    const float* Wdot    = (const float*)d_in[14];
    const float* Wout    = (const float*)d_in[15];
    const void*  eidx    = d_in[16];

    const int n = in_sizes[0] / 128;
    const int E = in_sizes[1] / 16;
    const int twoE = 2 * E;

    prep_kernel<<<(n * 32 + 255) / 256, 256>>>(eidx, twoE, n, Wq, Wdot,
                                               Wang_k, Wang_v);   // launch 1

    const int nb = (n + 63) / 64;
    q2_kernel<<<nb, 256>>>(na, n);                                // launch 2

    const int eb = (E + 63) / 64;
    cudaFuncSetAttribute(edge_kernel, cudaFuncAttributeMaxDynamicSharedMemorySize,
                         (int)(F_SMEM * sizeof(float)));
    edge_kernel<<<eb, 256, F_SMEM * sizeof(float)>>>(             // launch 3
        na, ea, shp, Wlin_k, W1k, b1k, W2k, Wlin_v, W1v, b1v, W2v, E);

    out_kernel<<<nb, 256>>>(Wout, (float*)d_out, n);              // launch 4
}